// round 1
// baseline (speedup 1.0000x reference)
#include <cuda_runtime.h>

// Problem constants (fixed by the reference)
#define NN    32768
#define EE    262144
#define OUTD  512
#define HH    8
#define DHH   64

// ---------------- scratch (device globals; no allocation allowed) ----------
__device__ float g_x[NN * OUTD];
__device__ float g_q[NN * OUTD];
__device__ float g_k[NN * OUTD];
__device__ float g_v[NN * OUTD];
__device__ int   g_cnt[NN];
__device__ int   g_off[NN + 1];
__device__ int   g_cur[NN];
__device__ int   g_eid[EE];

// ---------------- GEMM: C[M,512] = A[M,512] @ B[512,512], +bias, *scale ----
// 128x128 tile, BK=16, 256 threads, 8x8 microtile per thread.
__global__ __launch_bounds__(256, 2)
void gemm512(const float* __restrict__ A, const float* __restrict__ B,
             const float* __restrict__ bias, float* __restrict__ C,
             float scale)
{
    __shared__ float As[16][128];   // transposed A tile: As[k][m]
    __shared__ float Bs[16][128];   // Bs[k][n]

    const int tid  = threadIdx.x;
    const int tx   = tid & 15;      // 0..15 -> n
    const int ty   = tid >> 4;      // 0..15 -> m
    const int brow = blockIdx.y * 128;
    const int bcol = blockIdx.x * 128;

    // A-load mapping: 128 rows x 16 k, float4 per thread x2
    const int arow = tid >> 2;          // 0..63
    const int ak4  = (tid & 3) * 4;     // k offset 0,4,8,12
    // B-load mapping: 16 rows x 128 n, float4 per thread x2
    const int brL  = tid >> 5;          // 0..7
    const int bcL  = (tid & 31) * 4;    // 0..124

    float acc[8][8];
#pragma unroll
    for (int i = 0; i < 8; i++)
#pragma unroll
        for (int j = 0; j < 8; j++) acc[i][j] = 0.f;

    for (int k0 = 0; k0 < 512; k0 += 16) {
#pragma unroll
        for (int p = 0; p < 2; p++) {
            const int r = arow + p * 64;
            const float4 av = *(const float4*)(A + (size_t)(brow + r) * 512 + k0 + ak4);
            As[ak4 + 0][r] = av.x;
            As[ak4 + 1][r] = av.y;
            As[ak4 + 2][r] = av.z;
            As[ak4 + 3][r] = av.w;
        }
#pragma unroll
        for (int p = 0; p < 2; p++) {
            const int r = brL + p * 8;
            *(float4*)&Bs[r][bcL] = *(const float4*)(B + (size_t)(k0 + r) * 512 + bcol + bcL);
        }
        __syncthreads();

#pragma unroll
        for (int kk = 0; kk < 16; kk++) {
            const float4 a0 = *(const float4*)&As[kk][ty * 4];
            const float4 a1 = *(const float4*)&As[kk][64 + ty * 4];
            const float4 b0 = *(const float4*)&Bs[kk][tx * 4];
            const float4 b1 = *(const float4*)&Bs[kk][64 + tx * 4];
            const float a[8] = {a0.x, a0.y, a0.z, a0.w, a1.x, a1.y, a1.z, a1.w};
            const float b[8] = {b0.x, b0.y, b0.z, b0.w, b1.x, b1.y, b1.z, b1.w};
#pragma unroll
            for (int i = 0; i < 8; i++)
#pragma unroll
                for (int j = 0; j < 8; j++)
                    acc[i][j] = fmaf(a[i], b[j], acc[i][j]);
        }
        __syncthreads();
    }

    const float4 bs0 = *(const float4*)(bias + bcol + tx * 4);
    const float4 bs1 = *(const float4*)(bias + bcol + 64 + tx * 4);
    const float bb[8] = {bs0.x, bs0.y, bs0.z, bs0.w, bs1.x, bs1.y, bs1.z, bs1.w};

#pragma unroll
    for (int i = 0; i < 8; i++) {
        const int m = brow + ((i < 4) ? (ty * 4 + i) : (64 + ty * 4 + (i - 4)));
        float4 o0, o1;
        o0.x = (acc[i][0] + bb[0]) * scale;
        o0.y = (acc[i][1] + bb[1]) * scale;
        o0.z = (acc[i][2] + bb[2]) * scale;
        o0.w = (acc[i][3] + bb[3]) * scale;
        o1.x = (acc[i][4] + bb[4]) * scale;
        o1.y = (acc[i][5] + bb[5]) * scale;
        o1.z = (acc[i][6] + bb[6]) * scale;
        o1.w = (acc[i][7] + bb[7]) * scale;
        *(float4*)(C + (size_t)m * 512 + bcol + tx * 4)      = o0;
        *(float4*)(C + (size_t)m * 512 + bcol + 64 + tx * 4) = o1;
    }
}

// ---------------- CSR build -------------------------------------------------
__global__ void zero_cnt_kernel()
{
    const int i = blockIdx.x * blockDim.x + threadIdx.x;
    if (i < NN) g_cnt[i] = 0;
}

__global__ void count_kernel(const int* __restrict__ row)
{
    const int e = blockIdx.x * blockDim.x + threadIdx.x;
    if (e < EE) atomicAdd(&g_cnt[row[e]], 1);
}

// single-block exclusive scan over NN=32768 counts (512 threads x 64 each)
__global__ void scan_kernel()
{
    __shared__ int sh[512];
    const int t = threadIdx.x;
    const int base = t * 64;
    int s = 0;
#pragma unroll 4
    for (int i = 0; i < 64; i++) s += g_cnt[base + i];
    sh[t] = s;
    __syncthreads();
    for (int off = 1; off < 512; off <<= 1) {
        int v = (t >= off) ? sh[t - off] : 0;
        __syncthreads();
        sh[t] += v;
        __syncthreads();
    }
    int run = sh[t] - s;  // exclusive prefix of this chunk
    for (int i = 0; i < 64; i++) {
        g_off[base + i] = run;
        run += g_cnt[base + i];
    }
    if (t == 511) g_off[NN] = run;
}

__global__ void prep_cur_kernel()
{
    const int i = blockIdx.x * blockDim.x + threadIdx.x;
    if (i < NN) g_cur[i] = g_off[i];
}

__global__ void scatter_kernel(const int* __restrict__ row)
{
    const int e = blockIdx.x * blockDim.x + threadIdx.x;
    if (e < EE) {
        const int p = atomicAdd(&g_cur[row[e]], 1);
        g_eid[p] = e;
    }
}

// ---------------- fused SDDMM + online softmax + SPMM ----------------------
// one block per node, one warp per head; online softmax over the node's edges.
__global__ __launch_bounds__(256)
void attn_kernel(const int* __restrict__ col, float* __restrict__ out)
{
    const int node = blockIdx.x;
    const int head = threadIdx.x >> 5;
    const int lane = threadIdx.x & 31;
    const int beg = g_off[node];
    const int end = g_off[node + 1];

    const size_t hoff = (size_t)head * DHH + lane * 2;
    const float2 qv = *(const float2*)(g_q + (size_t)node * OUTD + hoff);

    float m = -3.402823466e38f;
    float den = 0.f;
    float2 acc = make_float2(0.f, 0.f);

    for (int j = beg; j < end; j++) {
        const int e = g_eid[j];
        const int c = col[e];
        const float2 kv = *(const float2*)(g_k + (size_t)c * OUTD + hoff);
        float s = qv.x * kv.x + qv.y * kv.y;
#pragma unroll
        for (int off = 16; off; off >>= 1)
            s += __shfl_xor_sync(0xffffffffu, s, off);
        const float2 vv = *(const float2*)(g_v + (size_t)c * OUTD + hoff);
        const float mn   = fmaxf(m, s);
        const float corr = __expf(m - mn);   // 0 on first edge (m = -inf-ish)
        const float p    = __expf(s - mn);
        den   = den * corr + p;
        acc.x = acc.x * corr + p * vv.x;
        acc.y = acc.y * corr + p * vv.y;
        m = mn;
    }

    const float inv = (den > 0.f) ? (1.f / den) : 0.f;  // degree-0 rows -> 0
    float2 o = make_float2(acc.x * inv, acc.y * inv);
    *(float2*)(out + (size_t)node * OUTD + hoff) = o;
}

// ---------------- launch ----------------------------------------------------
extern "C" void kernel_launch(void* const* d_in, const int* in_sizes, int n_in,
                              void* d_out, int out_size)
{
    const float* h    = (const float*)d_in[0];
    const int*   row  = (const int*)d_in[1];
    const int*   col  = (const int*)d_in[2];
    const float* W_in = (const float*)d_in[3];
    const float* b_in = (const float*)d_in[4];
    const float* W_q  = (const float*)d_in[5];
    const float* b_q  = (const float*)d_in[6];
    const float* W_k  = (const float*)d_in[7];
    const float* b_k  = (const float*)d_in[8];
    const float* W_v  = (const float*)d_in[9];
    const float* b_v  = (const float*)d_in[10];
    float* out = (float*)d_out;

    float *gx, *gq, *gk, *gv;
    cudaGetSymbolAddress((void**)&gx, g_x);
    cudaGetSymbolAddress((void**)&gq, g_q);
    cudaGetSymbolAddress((void**)&gk, g_k);
    cudaGetSymbolAddress((void**)&gv, g_v);

    const dim3 ggrid(512 / 128, NN / 128);  // (4, 256)
    gemm512<<<ggrid, 256>>>(h,  W_in, b_in, gx, 1.0f);
    gemm512<<<ggrid, 256>>>(gx, W_q,  b_q,  gq, 0.125f);  // DH^-0.5 = 1/8
    gemm512<<<ggrid, 256>>>(gx, W_k,  b_k,  gk, 1.0f);
    gemm512<<<ggrid, 256>>>(gx, W_v,  b_v,  gv, 1.0f);

    zero_cnt_kernel<<<NN / 256, 256>>>();
    count_kernel<<<EE / 256, 256>>>(row);
    scan_kernel<<<1, 512>>>();
    prep_cur_kernel<<<NN / 256, 256>>>();
    scatter_kernel<<<EE / 256, 256>>>(row);

    attn_kernel<<<NN, 256>>>(col, out);
}

// round 3
// speedup vs baseline: 1.8729x; 1.8729x over previous
#include <cuda_runtime.h>
#include <stdint.h>

// Problem constants (fixed by the reference)
#define NN    32768
#define EE    262144
#define OUTD  512
#define HH    8
#define DHH   64

// ---------------- scratch (device globals; no allocation allowed) ----------
__device__ float g_x[NN * OUTD];
__device__ float g_q[NN * OUTD];
__device__ float g_k[NN * OUTD];
__device__ float g_v[NN * OUTD];
__device__ int   g_cnt[NN];
__device__ int   g_off[NN + 1];
__device__ int   g_cur[NN];
__device__ int   g_eid[EE];

// ---------------- tf32 helpers ---------------------------------------------
__device__ __forceinline__ float cvt_rna_tf32(float x)
{
    float r;
    asm("cvt.rna.tf32.f32 %0, %1;" : "=f"(r) : "f"(x));
    return r;
}

__device__ __forceinline__ void mma_tf32(float* c, const uint32_t* a, const uint32_t* b)
{
    asm("mma.sync.aligned.m16n8k8.row.col.f32.tf32.tf32.f32 "
        "{%0,%1,%2,%3}, {%4,%5,%6,%7}, {%8,%9}, {%0,%1,%2,%3};"
        : "+f"(c[0]), "+f"(c[1]), "+f"(c[2]), "+f"(c[3])
        : "r"(a[0]), "r"(a[1]), "r"(a[2]), "r"(a[3]),
          "r"(b[0]), "r"(b[1]));
}

// ---------------- tf32 tensor-core GEMM ------------------------------------
// C[M,512] = (A[M,512] @ B[512,512] + bias) * scale
// CTA tile 128x128, BK=32, 8 warps as 2(m) x 4(n): warp tile 64x32.
// A in smem pair-permuted [m][k'] stride 40; B plain [k][n] stride 136.
#define BM 128
#define BN 128
#define BK 32
#define ASTR 40
#define BSTR 136
#define SMEM_BYTES ((2*BM*ASTR + 2*BK*BSTR) * 4)

__global__ __launch_bounds__(256)
void gemm_tf32(const float* __restrict__ A, const float* __restrict__ B,
               const float* __restrict__ bias, float* __restrict__ C,
               float scale)
{
    extern __shared__ float sm[];
    float* AsBase = sm;                    // [2][BM][ASTR]
    float* BsBase = sm + 2 * BM * ASTR;    // [2][BK][BSTR]

    const int tid  = threadIdx.x;
    const int lane = tid & 31;
    const int wid  = tid >> 5;
    const int brow = blockIdx.y * BM;
    const int bcol = blockIdx.x * BN;
    const int m0   = (wid >> 2) * 64;   // warp m offset (0, 64)
    const int n0   = (wid & 3) * 32;    // warp n offset (0,32,64,96)

    // A staging: thread loads float4 at rows ar+32p, cols ac4..ac4+3
    const int ar   = tid >> 3;          // 0..31
    const int ac4  = (tid & 7) * 4;     // 0,4,...,28
    const int ag   = ac4 >> 3;          // k-group 0..3
    const int apar = (ac4 >> 2) & 1;    // parity within group
    // B staging: thread loads float4 at rows brr+8p, cols bc4..bc4+3
    const int brr  = tid >> 5;          // 0..7
    const int bc4  = (tid & 31) * 4;    // 0..124

    const int lq = lane >> 2;           // 0..7
    const int lr = lane & 3;            // 0..3

    float acc[4][4][4];
#pragma unroll
    for (int mt = 0; mt < 4; mt++)
#pragma unroll
        for (int nt = 0; nt < 4; nt++)
#pragma unroll
            for (int r = 0; r < 4; r++) acc[mt][nt][r] = 0.f;

    float a_st[16], b_st[16];

    // ---- prologue: stage tile 0 ----
#pragma unroll
    for (int p = 0; p < 4; p++) {
        const float4 av = *(const float4*)(A + (size_t)(brow + ar + p * 32) * 512 + ac4);
        a_st[p*4+0] = av.x; a_st[p*4+1] = av.y; a_st[p*4+2] = av.z; a_st[p*4+3] = av.w;
        const float4 bv = *(const float4*)(B + (size_t)(brr + p * 8) * 512 + bcol + bc4);
        b_st[p*4+0] = bv.x; b_st[p*4+1] = bv.y; b_st[p*4+2] = bv.z; b_st[p*4+3] = bv.w;
    }
#pragma unroll
    for (int p = 0; p < 4; p++) {
#pragma unroll
        for (int j = 0; j < 4; j++)
            AsBase[(ar + p * 32) * ASTR + ag * 8 + 2 * j + apar] = cvt_rna_tf32(a_st[p*4+j]);
        float4 bw;
        bw.x = cvt_rna_tf32(b_st[p*4+0]); bw.y = cvt_rna_tf32(b_st[p*4+1]);
        bw.z = cvt_rna_tf32(b_st[p*4+2]); bw.w = cvt_rna_tf32(b_st[p*4+3]);
        *(float4*)&BsBase[(brr + p * 8) * BSTR + bc4] = bw;
    }
    __syncthreads();

    int cur = 0;
    for (int it = 0; it < 512 / BK; ++it) {
        // prefetch next K tile into registers
        if (it < 512 / BK - 1) {
            const int k0 = (it + 1) * BK;
#pragma unroll
            for (int p = 0; p < 4; p++) {
                const float4 av = *(const float4*)(A + (size_t)(brow + ar + p * 32) * 512 + k0 + ac4);
                a_st[p*4+0] = av.x; a_st[p*4+1] = av.y; a_st[p*4+2] = av.z; a_st[p*4+3] = av.w;
                const float4 bv = *(const float4*)(B + (size_t)(k0 + brr + p * 8) * 512 + bcol + bc4);
                b_st[p*4+0] = bv.x; b_st[p*4+1] = bv.y; b_st[p*4+2] = bv.z; b_st[p*4+3] = bv.w;
            }
        }

        // compute on current buffer
        const float* Ac = AsBase + cur * BM * ASTR;
        const float* Bc = BsBase + cur * BK * BSTR;
#pragma unroll
        for (int g = 0; g < 4; ++g) {
            uint32_t bf[4][2];
#pragma unroll
            for (int nt = 0; nt < 4; nt++) {
                const int n = n0 + nt * 8 + lq;
                bf[nt][0] = __float_as_uint(Bc[(g * 8 + lr) * BSTR + n]);
                bf[nt][1] = __float_as_uint(Bc[(g * 8 + 4 + lr) * BSTR + n]);
            }
#pragma unroll
            for (int mt = 0; mt < 4; mt++) {
                const int row = m0 + mt * 16 + lq;
                const float2 p0 = *(const float2*)&Ac[row * ASTR + g * 8 + lr * 2];
                const float2 p1 = *(const float2*)&Ac[(row + 8) * ASTR + g * 8 + lr * 2];
                uint32_t af[4] = {__float_as_uint(p0.x), __float_as_uint(p1.x),
                                  __float_as_uint(p0.y), __float_as_uint(p1.y)};
#pragma unroll
                for (int nt = 0; nt < 4; nt++)
                    mma_tf32(acc[mt][nt], af, bf[nt]);
            }
        }

        // store prefetched tile into the other buffer
        if (it < 512 / BK - 1) {
            const int nxt = cur ^ 1;
            float* An = AsBase + nxt * BM * ASTR;
            float* Bn = BsBase + nxt * BK * BSTR;
#pragma unroll
            for (int p = 0; p < 4; p++) {
#pragma unroll
                for (int j = 0; j < 4; j++)
                    An[(ar + p * 32) * ASTR + ag * 8 + 2 * j + apar] = cvt_rna_tf32(a_st[p*4+j]);
                float4 bw;
                bw.x = cvt_rna_tf32(b_st[p*4+0]); bw.y = cvt_rna_tf32(b_st[p*4+1]);
                bw.z = cvt_rna_tf32(b_st[p*4+2]); bw.w = cvt_rna_tf32(b_st[p*4+3]);
                *(float4*)&Bn[(brr + p * 8) * BSTR + bc4] = bw;
            }
            __syncthreads();
            cur = nxt;
        }
    }

    // ---- epilogue: bias + scale, float2 stores ----
#pragma unroll
    for (int mt = 0; mt < 4; mt++) {
        const int row = brow + m0 + mt * 16 + lq;
#pragma unroll
        for (int nt = 0; nt < 4; nt++) {
            const int colb = bcol + n0 + nt * 8 + 2 * lr;
            const float b0 = bias[colb];
            const float b1 = bias[colb + 1];
            float2 o0, o1;
            o0.x = (acc[mt][nt][0] + b0) * scale;
            o0.y = (acc[mt][nt][1] + b1) * scale;
            o1.x = (acc[mt][nt][2] + b0) * scale;
            o1.y = (acc[mt][nt][3] + b1) * scale;
            *(float2*)(C + (size_t)row * 512 + colb)       = o0;
            *(float2*)(C + (size_t)(row + 8) * 512 + colb) = o1;
        }
    }
}

// ---------------- CSR build -------------------------------------------------
__global__ void zero_cnt_kernel()
{
    const int i = blockIdx.x * blockDim.x + threadIdx.x;
    if (i < NN) g_cnt[i] = 0;
}

__global__ void count_kernel(const int* __restrict__ row)
{
    const int e = blockIdx.x * blockDim.x + threadIdx.x;
    if (e < EE) atomicAdd(&g_cnt[row[e]], 1);
}

// single-block exclusive scan over NN=32768 counts (512 threads x 64 each)
__global__ void scan_kernel()
{
    __shared__ int sh[512];
    const int t = threadIdx.x;
    const int base = t * 64;
    int s = 0;
#pragma unroll 4
    for (int i = 0; i < 64; i++) s += g_cnt[base + i];
    sh[t] = s;
    __syncthreads();
    for (int off = 1; off < 512; off <<= 1) {
        int v = (t >= off) ? sh[t - off] : 0;
        __syncthreads();
        sh[t] += v;
        __syncthreads();
    }
    int run = sh[t] - s;  // exclusive prefix of this chunk
    for (int i = 0; i < 64; i++) {
        g_off[base + i] = run;
        run += g_cnt[base + i];
    }
    if (t == 511) g_off[NN] = run;
}

__global__ void prep_cur_kernel()
{
    const int i = blockIdx.x * blockDim.x + threadIdx.x;
    if (i < NN) g_cur[i] = g_off[i];
}

__global__ void scatter_kernel(const int* __restrict__ row)
{
    const int e = blockIdx.x * blockDim.x + threadIdx.x;
    if (e < EE) {
        const int p = atomicAdd(&g_cur[row[e]], 1);
        g_eid[p] = e;
    }
}

// ---------------- fused SDDMM + online softmax + SPMM ----------------------
__global__ __launch_bounds__(256)
void attn_kernel(const int* __restrict__ col, float* __restrict__ out)
{
    const int node = blockIdx.x;
    const int head = threadIdx.x >> 5;
    const int lane = threadIdx.x & 31;
    const int beg = g_off[node];
    const int end = g_off[node + 1];

    const size_t hoff = (size_t)head * DHH + lane * 2;
    const float2 qv = *(const float2*)(g_q + (size_t)node * OUTD + hoff);

    float m = -3.402823466e38f;
    float den = 0.f;
    float2 acc = make_float2(0.f, 0.f);

    for (int j = beg; j < end; j++) {
        const int e = g_eid[j];
        const int c = col[e];
        const float2 kv = *(const float2*)(g_k + (size_t)c * OUTD + hoff);
        float s = qv.x * kv.x + qv.y * kv.y;
#pragma unroll
        for (int off = 16; off; off >>= 1)
            s += __shfl_xor_sync(0xffffffffu, s, off);
        const float2 vv = *(const float2*)(g_v + (size_t)c * OUTD + hoff);
        const float mn   = fmaxf(m, s);
        const float corr = __expf(m - mn);
        const float p    = __expf(s - mn);
        den   = den * corr + p;
        acc.x = acc.x * corr + p * vv.x;
        acc.y = acc.y * corr + p * vv.y;
        m = mn;
    }

    const float inv = (den > 0.f) ? (1.f / den) : 0.f;
    float2 o = make_float2(acc.x * inv, acc.y * inv);
    *(float2*)(out + (size_t)node * OUTD + hoff) = o;
}

// ---------------- launch ----------------------------------------------------
extern "C" void kernel_launch(void* const* d_in, const int* in_sizes, int n_in,
                              void* d_out, int out_size)
{
    const float* h    = (const float*)d_in[0];
    const int*   row  = (const int*)d_in[1];
    const int*   col  = (const int*)d_in[2];
    const float* W_in = (const float*)d_in[3];
    const float* b_in = (const float*)d_in[4];
    const float* W_q  = (const float*)d_in[5];
    const float* b_q  = (const float*)d_in[6];
    const float* W_k  = (const float*)d_in[7];
    const float* b_k  = (const float*)d_in[8];
    const float* W_v  = (const float*)d_in[9];
    const float* b_v  = (const float*)d_in[10];
    float* out = (float*)d_out;

    float *gx, *gq, *gk, *gv;
    cudaGetSymbolAddress((void**)&gx, g_x);
    cudaGetSymbolAddress((void**)&gq, g_q);
    cudaGetSymbolAddress((void**)&gk, g_k);
    cudaGetSymbolAddress((void**)&gv, g_v);

    cudaFuncSetAttribute(gemm_tf32, cudaFuncAttributeMaxDynamicSharedMemorySize, SMEM_BYTES);

    const dim3 ggrid(512 / BN, NN / BM);  // (4, 256)
    gemm_tf32<<<ggrid, 256, SMEM_BYTES>>>(h,  W_in, b_in, gx, 1.0f);
    gemm_tf32<<<ggrid, 256, SMEM_BYTES>>>(gx, W_q,  b_q,  gq, 0.125f);
    gemm_tf32<<<ggrid, 256, SMEM_BYTES>>>(gx, W_k,  b_k,  gk, 1.0f);
    gemm_tf32<<<ggrid, 256, SMEM_BYTES>>>(gx, W_v,  b_v,  gv, 1.0f);

    zero_cnt_kernel<<<NN / 256, 256>>>();
    count_kernel<<<EE / 256, 256>>>(row);
    scan_kernel<<<1, 512>>>();
    prep_cur_kernel<<<NN / 256, 256>>>();
    scatter_kernel<<<EE / 256, 256>>>(row);

    attn_kernel<<<NN, 256>>>(col, out);
}

// round 5
// speedup vs baseline: 1.9830x; 1.0588x over previous
#include <cuda_runtime.h>
#include <stdint.h>

// Problem constants (fixed by the reference)
#define NN    32768
#define EE    262144
#define OUTD  512
#define HH    8
#define DHH   64

// ---------------- scratch (device globals; no allocation allowed) ----------
__device__ float g_x[NN * OUTD];
__device__ float g_q[NN * OUTD];
__device__ float g_k[NN * OUTD];
__device__ float g_v[NN * OUTD];
__device__ int   g_cnt[NN];
__device__ int   g_off[NN + 1];
__device__ int   g_cur[NN];
__device__ int   g_ecol[EE];

// ---------------- tf32 helpers ---------------------------------------------
__device__ __forceinline__ float cvt_rna_tf32(float x)
{
    float r;
    asm("cvt.rna.tf32.f32 %0, %1;" : "=f"(r) : "f"(x));
    return r;
}

__device__ __forceinline__ void mma_tf32(float* c, const uint32_t* a, const uint32_t* b)
{
    asm("mma.sync.aligned.m16n8k8.row.col.f32.tf32.tf32.f32 "
        "{%0,%1,%2,%3}, {%4,%5,%6,%7}, {%8,%9}, {%0,%1,%2,%3};"
        : "+f"(c[0]), "+f"(c[1]), "+f"(c[2]), "+f"(c[3])
        : "r"(a[0]), "r"(a[1]), "r"(a[2]), "r"(a[3]),
          "r"(b[0]), "r"(b[1]));
}

// ---------------- tf32 tensor-core GEMM ------------------------------------
// C[M,512] = (A[M,512] @ B[512,512] + bias) * scale
// CTA tile 128x128, BK=16, 8 warps as 2(m) x 4(n): warp tile 64x32.
// A smem pair-permuted [m][k'] stride 36; B plain [k][n] stride 136.
// __launch_bounds__(256,2): cap regs at 128 so 2 CTAs/SM fit the regfile.
#define BM 128
#define BN 128
#define BK 16
#define ASTR 36
#define BSTR 136
#define SMEM_BYTES ((2*BM*ASTR + 2*BK*BSTR) * 4)

__global__ __launch_bounds__(256, 2)
void gemm_tf32(const float* __restrict__ A, const float* __restrict__ B,
               const float* __restrict__ bias, float* __restrict__ C,
               float scale)
{
    extern __shared__ float sm[];
    float* AsBase = sm;                    // [2][BM][ASTR]
    float* BsBase = sm + 2 * BM * ASTR;    // [2][BK][BSTR]

    const int tid  = threadIdx.x;
    const int lane = tid & 31;
    const int wid  = tid >> 5;
    const int brow = blockIdx.y * BM;
    const int bcol = blockIdx.x * BN;
    const int m0   = (wid >> 2) * 64;   // warp m offset (0, 64)
    const int n0   = (wid & 3) * 32;    // warp n offset (0,32,64,96)

    // A staging: thread loads float4 at rows ar+64p, cols ak4..ak4+3
    const int ar   = tid >> 2;          // 0..63
    const int ak4  = (tid & 3) * 4;     // 0,4,8,12
    const int ag   = ak4 >> 3;          // k-group 0..1
    const int apar = (ak4 >> 2) & 1;    // parity within group
    // B staging: thread loads float4 at rows brr+8p, cols bc4..bc4+3
    const int brr  = tid >> 5;          // 0..7
    const int bc4  = (tid & 31) * 4;    // 0..124

    const int lq = lane >> 2;           // 0..7
    const int lr = lane & 3;            // 0..3

    float acc[4][4][4];
#pragma unroll
    for (int mt = 0; mt < 4; mt++)
#pragma unroll
        for (int nt = 0; nt < 4; nt++)
#pragma unroll
            for (int r = 0; r < 4; r++) acc[mt][nt][r] = 0.f;

    float a_st[8], b_st[8];

    // ---- prologue: stage tile 0 ----
#pragma unroll
    for (int p = 0; p < 2; p++) {
        const float4 av = *(const float4*)(A + (size_t)(brow + ar + p * 64) * 512 + ak4);
        a_st[p*4+0] = av.x; a_st[p*4+1] = av.y; a_st[p*4+2] = av.z; a_st[p*4+3] = av.w;
        const float4 bv = *(const float4*)(B + (size_t)(brr + p * 8) * 512 + bcol + bc4);
        b_st[p*4+0] = bv.x; b_st[p*4+1] = bv.y; b_st[p*4+2] = bv.z; b_st[p*4+3] = bv.w;
    }
#pragma unroll
    for (int p = 0; p < 2; p++) {
#pragma unroll
        for (int j = 0; j < 4; j++)
            AsBase[(ar + p * 64) * ASTR + ag * 8 + 2 * j + apar] = cvt_rna_tf32(a_st[p*4+j]);
        float4 bw;
        bw.x = cvt_rna_tf32(b_st[p*4+0]); bw.y = cvt_rna_tf32(b_st[p*4+1]);
        bw.z = cvt_rna_tf32(b_st[p*4+2]); bw.w = cvt_rna_tf32(b_st[p*4+3]);
        *(float4*)&BsBase[(brr + p * 8) * BSTR + bc4] = bw;
    }
    __syncthreads();

    int cur = 0;
    for (int it = 0; it < 512 / BK; ++it) {
        // prefetch next K tile into registers
        if (it < 512 / BK - 1) {
            const int k0 = (it + 1) * BK;
#pragma unroll
            for (int p = 0; p < 2; p++) {
                const float4 av = *(const float4*)(A + (size_t)(brow + ar + p * 64) * 512 + k0 + ak4);
                a_st[p*4+0] = av.x; a_st[p*4+1] = av.y; a_st[p*4+2] = av.z; a_st[p*4+3] = av.w;
                const float4 bv = *(const float4*)(B + (size_t)(k0 + brr + p * 8) * 512 + bcol + bc4);
                b_st[p*4+0] = bv.x; b_st[p*4+1] = bv.y; b_st[p*4+2] = bv.z; b_st[p*4+3] = bv.w;
            }
        }

        // compute on current buffer (2 k-groups of 8)
        const float* Ac = AsBase + cur * BM * ASTR;
        const float* Bc = BsBase + cur * BK * BSTR;
#pragma unroll
        for (int g = 0; g < 2; ++g) {
            uint32_t bf[4][2];
#pragma unroll
            for (int nt = 0; nt < 4; nt++) {
                const int n = n0 + nt * 8 + lq;
                bf[nt][0] = __float_as_uint(Bc[(g * 8 + lr) * BSTR + n]);
                bf[nt][1] = __float_as_uint(Bc[(g * 8 + 4 + lr) * BSTR + n]);
            }
#pragma unroll
            for (int mt = 0; mt < 4; mt++) {
                const int row = m0 + mt * 16 + lq;
                const float2 p0 = *(const float2*)&Ac[row * ASTR + g * 8 + lr * 2];
                const float2 p1 = *(const float2*)&Ac[(row + 8) * ASTR + g * 8 + lr * 2];
                uint32_t af[4] = {__float_as_uint(p0.x), __float_as_uint(p1.x),
                                  __float_as_uint(p0.y), __float_as_uint(p1.y)};
#pragma unroll
                for (int nt = 0; nt < 4; nt++)
                    mma_tf32(acc[mt][nt], af, bf[nt]);
            }
        }

        // store prefetched tile into the other buffer
        if (it < 512 / BK - 1) {
            const int nxt = cur ^ 1;
            float* An = AsBase + nxt * BM * ASTR;
            float* Bn = BsBase + nxt * BK * BSTR;
#pragma unroll
            for (int p = 0; p < 2; p++) {
#pragma unroll
                for (int j = 0; j < 4; j++)
                    An[(ar + p * 64) * ASTR + ag * 8 + 2 * j + apar] = cvt_rna_tf32(a_st[p*4+j]);
                float4 bw;
                bw.x = cvt_rna_tf32(b_st[p*4+0]); bw.y = cvt_rna_tf32(b_st[p*4+1]);
                bw.z = cvt_rna_tf32(b_st[p*4+2]); bw.w = cvt_rna_tf32(b_st[p*4+3]);
                *(float4*)&Bn[(brr + p * 8) * BSTR + bc4] = bw;
            }
            __syncthreads();
            cur = nxt;
        }
    }

    // ---- epilogue: bias + scale, float2 stores ----
#pragma unroll
    for (int mt = 0; mt < 4; mt++) {
        const int row = brow + m0 + mt * 16 + lq;
#pragma unroll
        for (int nt = 0; nt < 4; nt++) {
            const int colb = bcol + n0 + nt * 8 + 2 * lr;
            const float b0 = __ldg(bias + colb);
            const float b1 = __ldg(bias + colb + 1);
            float2 o0, o1;
            o0.x = (acc[mt][nt][0] + b0) * scale;
            o0.y = (acc[mt][nt][1] + b1) * scale;
            o1.x = (acc[mt][nt][2] + b0) * scale;
            o1.y = (acc[mt][nt][3] + b1) * scale;
            *(float2*)(C + (size_t)row * 512 + colb)       = o0;
            *(float2*)(C + (size_t)(row + 8) * 512 + colb) = o1;
        }
    }
}

// ---------------- CSR build -------------------------------------------------
__global__ void zero_cnt_kernel()
{
    const int i = blockIdx.x * blockDim.x + threadIdx.x;
    if (i < NN) g_cnt[i] = 0;
}

__global__ void count_kernel(const int* __restrict__ row)
{
    const int e = blockIdx.x * blockDim.x + threadIdx.x;
    if (e < EE) atomicAdd(&g_cnt[row[e]], 1);
}

// single-block exclusive scan over NN=32768 counts (512 threads x 64 each)
// also writes g_cur (fused prep_cur)
__global__ void scan_kernel()
{
    __shared__ int sh[512];
    const int t = threadIdx.x;
    const int base = t * 64;
    int s = 0;
#pragma unroll 4
    for (int i = 0; i < 64; i++) s += g_cnt[base + i];
    sh[t] = s;
    __syncthreads();
    for (int off = 1; off < 512; off <<= 1) {
        int v = (t >= off) ? sh[t - off] : 0;
        __syncthreads();
        sh[t] += v;
        __syncthreads();
    }
    int run = sh[t] - s;  // exclusive prefix of this chunk
    for (int i = 0; i < 64; i++) {
        g_off[base + i] = run;
        g_cur[base + i] = run;
        run += g_cnt[base + i];
    }
    if (t == 511) g_off[NN] = run;
}

// scatter the COLUMN value directly (skips the eid indirection in attn)
__global__ void scatter_kernel(const int* __restrict__ row, const int* __restrict__ col)
{
    const int e = blockIdx.x * blockDim.x + threadIdx.x;
    if (e < EE) {
        const int p = atomicAdd(&g_cur[row[e]], 1);
        g_ecol[p] = col[e];
    }
}

// ---------------- fused SDDMM + online softmax + SPMM ----------------------
// one block per node, one warp per head; 2-edge-unrolled online softmax
// (two independent states halve the serial dependent chain), merged at end.
__global__ __launch_bounds__(256)
void attn_kernel(float* __restrict__ out)
{
    const int node = blockIdx.x;
    const int head = threadIdx.x >> 5;
    const int lane = threadIdx.x & 31;
    const int beg = g_off[node];
    const int end = g_off[node + 1];

    const size_t hoff = (size_t)head * DHH + lane * 2;
    const float2 qv = *(const float2*)(g_q + (size_t)node * OUTD + hoff);

    const float NEG = -3.402823466e38f;
    float m1 = NEG, den1 = 0.f;
    float2 acc1 = make_float2(0.f, 0.f);
    float m2 = NEG, den2 = 0.f;
    float2 acc2 = make_float2(0.f, 0.f);

    int j = beg;
    for (; j + 1 < end; j += 2) {
        const int ca = __ldg(g_ecol + j);
        const int cb = __ldg(g_ecol + j + 1);
        const float2 ka = *(const float2*)(g_k + (size_t)ca * OUTD + hoff);
        const float2 kb = *(const float2*)(g_k + (size_t)cb * OUTD + hoff);
        float sa = qv.x * ka.x + qv.y * ka.y;
        float sb = qv.x * kb.x + qv.y * kb.y;
#pragma unroll
        for (int off = 16; off; off >>= 1) {
            sa += __shfl_xor_sync(0xffffffffu, sa, off);
            sb += __shfl_xor_sync(0xffffffffu, sb, off);
        }
        const float2 va = *(const float2*)(g_v + (size_t)ca * OUTD + hoff);
        const float2 vb = *(const float2*)(g_v + (size_t)cb * OUTD + hoff);

        const float mna = fmaxf(m1, sa);
        const float ca1 = __expf(m1 - mna);
        const float pa  = __expf(sa - mna);
        den1   = den1 * ca1 + pa;
        acc1.x = acc1.x * ca1 + pa * va.x;
        acc1.y = acc1.y * ca1 + pa * va.y;
        m1 = mna;

        const float mnb = fmaxf(m2, sb);
        const float cb1 = __expf(m2 - mnb);
        const float pb  = __expf(sb - mnb);
        den2   = den2 * cb1 + pb;
        acc2.x = acc2.x * cb1 + pb * vb.x;
        acc2.y = acc2.y * cb1 + pb * vb.y;
        m2 = mnb;
    }
    if (j < end) {  // last odd edge into state 1
        const int ca = __ldg(g_ecol + j);
        const float2 ka = *(const float2*)(g_k + (size_t)ca * OUTD + hoff);
        float sa = qv.x * ka.x + qv.y * ka.y;
#pragma unroll
        for (int off = 16; off; off >>= 1)
            sa += __shfl_xor_sync(0xffffffffu, sa, off);
        const float2 va = *(const float2*)(g_v + (size_t)ca * OUTD + hoff);
        const float mna = fmaxf(m1, sa);
        const float ca1 = __expf(m1 - mna);
        const float pa  = __expf(sa - mna);
        den1   = den1 * ca1 + pa;
        acc1.x = acc1.x * ca1 + pa * va.x;
        acc1.y = acc1.y * ca1 + pa * va.y;
        m1 = mna;
    }

    // merge the two states
    const float mm = fmaxf(m1, m2);
    const float c1 = __expf(m1 - mm);
    const float c2 = __expf(m2 - mm);
    const float den = den1 * c1 + den2 * c2;
    float2 acc;
    acc.x = acc1.x * c1 + acc2.x * c2;
    acc.y = acc1.y * c1 + acc2.y * c2;

    const float inv = (den > 0.f) ? (1.f / den) : 0.f;
    float2 o = make_float2(acc.x * inv, acc.y * inv);
    *(float2*)(out + (size_t)node * OUTD + hoff) = o;
}

// ---------------- launch ----------------------------------------------------
extern "C" void kernel_launch(void* const* d_in, const int* in_sizes, int n_in,
                              void* d_out, int out_size)
{
    const float* h    = (const float*)d_in[0];
    const int*   row  = (const int*)d_in[1];
    const int*   col  = (const int*)d_in[2];
    const float* W_in = (const float*)d_in[3];
    const float* b_in = (const float*)d_in[4];
    const float* W_q  = (const float*)d_in[5];
    const float* b_q  = (const float*)d_in[6];
    const float* W_k  = (const float*)d_in[7];
    const float* b_k  = (const float*)d_in[8];
    const float* W_v  = (const float*)d_in[9];
    const float* b_v  = (const float*)d_in[10];
    float* out = (float*)d_out;

    float *gx, *gq, *gk, *gv;
    cudaGetSymbolAddress((void**)&gx, g_x);
    cudaGetSymbolAddress((void**)&gq, g_q);
    cudaGetSymbolAddress((void**)&gk, g_k);
    cudaGetSymbolAddress((void**)&gv, g_v);

    cudaFuncSetAttribute(gemm_tf32, cudaFuncAttributeMaxDynamicSharedMemorySize, SMEM_BYTES);

    const dim3 ggrid(512 / BN, NN / BM);  // (4, 256)
    gemm_tf32<<<ggrid, 256, SMEM_BYTES>>>(h,  W_in, b_in, gx, 1.0f);
    gemm_tf32<<<ggrid, 256, SMEM_BYTES>>>(gx, W_q,  b_q,  gq, 0.125f);
    gemm_tf32<<<ggrid, 256, SMEM_BYTES>>>(gx, W_k,  b_k,  gk, 1.0f);
    gemm_tf32<<<ggrid, 256, SMEM_BYTES>>>(gx, W_v,  b_v,  gv, 1.0f);

    zero_cnt_kernel<<<NN / 256, 256>>>();
    count_kernel<<<EE / 256, 256>>>(row);
    scan_kernel<<<1, 512>>>();
    scatter_kernel<<<EE / 256, 256>>>(row, col);

    attn_kernel<<<NN, 256>>>(out);
}

// round 7
// speedup vs baseline: 2.5577x; 1.2898x over previous
#include <cuda_runtime.h>
#include <stdint.h>

// Problem constants (fixed by the reference)
#define NN    32768
#define EE    262144
#define OUTD  512
#define HH    8
#define DHH   64

// ---------------- scratch (device globals; no allocation allowed) ----------
__device__ float g_wr[4 * OUTD * OUTD];   // RNA-rounded weights
__device__ float g_x[NN * OUTD];          // x, stored already tf32-rounded
__device__ float g_q[NN * OUTD];
__device__ float g_k[NN * OUTD];
__device__ float g_v[NN * OUTD];
__device__ int   g_cnt[NN];
__device__ int   g_off[NN + 1];
__device__ int   g_cur[NN];
__device__ int   g_ecol[EE];

// ---------------- tf32 helpers ---------------------------------------------
__device__ __forceinline__ float cvt_rna_tf32(float x)
{
    float r;
    asm("cvt.rna.tf32.f32 %0, %1;" : "=f"(r) : "f"(x));
    return r;
}

__device__ __forceinline__ void mma_tf32(float* c, const uint32_t* a, const uint32_t* b)
{
    asm("mma.sync.aligned.m16n8k8.row.col.f32.tf32.tf32.f32 "
        "{%0,%1,%2,%3}, {%4,%5,%6,%7}, {%8,%9}, {%0,%1,%2,%3};"
        : "+f"(c[0]), "+f"(c[1]), "+f"(c[2]), "+f"(c[3])
        : "r"(a[0]), "r"(a[1]), "r"(a[2]), "r"(a[3]),
          "r"(b[0]), "r"(b[1]));
}

__device__ __forceinline__ void cp16(uint32_t dst, const float* src)
{
    asm volatile("cp.async.cg.shared.global [%0], [%1], 16;\n" :: "r"(dst), "l"(src));
}
#define CP_COMMIT()  asm volatile("cp.async.commit_group;\n" ::: "memory")
#define CP_WAIT1()   asm volatile("cp.async.wait_group 1;\n" ::: "memory")

// ---------------- prep: RNA-round weight matrices ---------------------------
__global__ void round_copy4(const float4* __restrict__ src, float4* __restrict__ dst, int n4)
{
    const int i = blockIdx.x * blockDim.x + threadIdx.x;
    if (i < n4) {
        float4 v = src[i];
        v.x = cvt_rna_tf32(v.x); v.y = cvt_rna_tf32(v.y);
        v.z = cvt_rna_tf32(v.z); v.w = cvt_rna_tf32(v.w);
        dst[i] = v;
    }
}

// ---------------- tf32 tensor-core GEMM (cp.async, warp tile 64x64) ---------
// C[M,512] = (A[M,512] @ B[512,512] + bias) * scale
// CTA 128x128, BK=32, 4 warps in 2x2 grid of 64x64 warp tiles, 3-stage pipeline.
// A smem [m][k] stride 36 (bank = 4m+k); B smem [k][n] stride 136 (bank = 8k+n).
#define BM 128
#define BN 128
#define BK 32
#define ASTR 36
#define BSTR 136
#define AS_STG (BM * ASTR)          // 4608 floats
#define BS_STG (BK * BSTR)          // 4352 floats
#define STG    (AS_STG + BS_STG)    // 8960 floats
#define NSTAGE 3
#define GSMEM_BYTES (NSTAGE * STG * 4)   // 107520 B
#define KITERS (512 / BK)           // 16

template<bool ROUND_OUT>
__global__ __launch_bounds__(128, 2)
void gemm_tf32(const float* __restrict__ A, const float* __restrict__ B,
               const float* __restrict__ bias, float* __restrict__ C,
               float scale)
{
    extern __shared__ float sm[];
    const uint32_t smem_u = (uint32_t)__cvta_generic_to_shared(sm);

    const int tid  = threadIdx.x;
    const int lane = tid & 31;
    const int wid  = tid >> 5;
    const int brow = blockIdx.y * BM;
    const int bcol = blockIdx.x * BN;
    const int m0   = (wid >> 1) * 64;   // 0, 64
    const int n0   = (wid & 1) * 64;    // 0, 64
    const int lq   = lane >> 2;         // 0..7
    const int lr   = lane & 3;          // 0..3

    // cp.async mappings (128 threads)
    const int a_kc = tid & 7;           // A chunk within row (8 x 16B)
    const int a_r0 = tid >> 3;          // A row 0..15 (+16p)
    const int b_kc = tid & 31;          // B chunk within row (32 x 16B)
    const int b_r0 = tid >> 5;          // B k-row 0..3 (+4p)

    float acc[4][8][4];
#pragma unroll
    for (int mt = 0; mt < 4; mt++)
#pragma unroll
        for (int nt = 0; nt < 8; nt++)
#pragma unroll
            for (int r = 0; r < 4; r++) acc[mt][nt][r] = 0.f;

    // stage loader
    auto load_stage = [&](int s, int kt) {
        const int k0 = kt * BK;
        const uint32_t abase = smem_u + (uint32_t)(s * STG) * 4u;
        const uint32_t bbase = abase + (uint32_t)AS_STG * 4u;
#pragma unroll
        for (int p = 0; p < 8; p++) {
            const int m = a_r0 + p * 16;
            cp16(abase + (uint32_t)(m * ASTR + a_kc * 4) * 4u,
                 A + (size_t)(brow + m) * 512 + k0 + a_kc * 4);
        }
#pragma unroll
        for (int p = 0; p < 8; p++) {
            const int k = b_r0 + p * 4;
            cp16(bbase + (uint32_t)(k * BSTR + b_kc * 4) * 4u,
                 B + (size_t)(k0 + k) * 512 + bcol + b_kc * 4);
        }
    };

    load_stage(0, 0); CP_COMMIT();
    load_stage(1, 1); CP_COMMIT();

    int st = 0;
    for (int it = 0; it < KITERS; ++it) {
        CP_WAIT1();
        __syncthreads();

        const float* As = sm + st * STG;
        const float* Bs = As + AS_STG;

#pragma unroll
        for (int g = 0; g < 4; ++g) {
            uint32_t bf[8][2];
#pragma unroll
            for (int nt = 0; nt < 8; nt++) {
                const int n = n0 + nt * 8 + lq;
                bf[nt][0] = __float_as_uint(Bs[(g * 8 + lr) * BSTR + n]);
                bf[nt][1] = __float_as_uint(Bs[(g * 8 + 4 + lr) * BSTR + n]);
            }
#pragma unroll
            for (int mt = 0; mt < 4; mt++) {
                const int row = m0 + mt * 16 + lq;
                uint32_t af[4];
                af[0] = __float_as_uint(As[(row)     * ASTR + g * 8 + lr]);
                af[1] = __float_as_uint(As[(row + 8) * ASTR + g * 8 + lr]);
                af[2] = __float_as_uint(As[(row)     * ASTR + g * 8 + 4 + lr]);
                af[3] = __float_as_uint(As[(row + 8) * ASTR + g * 8 + 4 + lr]);
#pragma unroll
                for (int nt = 0; nt < 8; nt++)
                    mma_tf32(acc[mt][nt], af, bf[nt]);
            }
        }

        const int nx = it + 2;
        if (nx < KITERS) load_stage((nx >= NSTAGE) ? (nx - NSTAGE * (nx / NSTAGE)) : nx, nx);
        CP_COMMIT();
        st = (st == NSTAGE - 1) ? 0 : st + 1;
    }

    // ---- epilogue: bias + scale (+optional tf32 rounding), float2 stores ----
#pragma unroll
    for (int mt = 0; mt < 4; mt++) {
        const int row = brow + m0 + mt * 16 + lq;
#pragma unroll
        for (int nt = 0; nt < 8; nt++) {
            const int colb = bcol + n0 + nt * 8 + 2 * lr;
            const float b0 = __ldg(bias + colb);
            const float b1 = __ldg(bias + colb + 1);
            float2 o0, o1;
            o0.x = (acc[mt][nt][0] + b0) * scale;
            o0.y = (acc[mt][nt][1] + b1) * scale;
            o1.x = (acc[mt][nt][2] + b0) * scale;
            o1.y = (acc[mt][nt][3] + b1) * scale;
            if (ROUND_OUT) {
                o0.x = cvt_rna_tf32(o0.x); o0.y = cvt_rna_tf32(o0.y);
                o1.x = cvt_rna_tf32(o1.x); o1.y = cvt_rna_tf32(o1.y);
            }
            *(float2*)(C + (size_t)row * 512 + colb)       = o0;
            *(float2*)(C + (size_t)(row + 8) * 512 + colb) = o1;
        }
    }
}

// ---------------- CSR build -------------------------------------------------
__global__ void zero_cnt_kernel()
{
    const int i = blockIdx.x * blockDim.x + threadIdx.x;
    if (i < NN) g_cnt[i] = 0;
}

__global__ void count_kernel(const int* __restrict__ row)
{
    const int e = blockIdx.x * blockDim.x + threadIdx.x;
    if (e < EE) atomicAdd(&g_cnt[row[e]], 1);
}

// single-block exclusive scan over NN=32768 counts (512 threads x 64 each)
__global__ void scan_kernel()
{
    __shared__ int sh[512];
    const int t = threadIdx.x;
    const int base = t * 64;
    int s = 0;
#pragma unroll 4
    for (int i = 0; i < 64; i++) s += g_cnt[base + i];
    sh[t] = s;
    __syncthreads();
    for (int off = 1; off < 512; off <<= 1) {
        int v = (t >= off) ? sh[t - off] : 0;
        __syncthreads();
        sh[t] += v;
        __syncthreads();
    }
    int run = sh[t] - s;
    for (int i = 0; i < 64; i++) {
        g_off[base + i] = run;
        g_cur[base + i] = run;
        run += g_cnt[base + i];
    }
    if (t == 511) g_off[NN] = run;
}

__global__ void scatter_kernel(const int* __restrict__ row, const int* __restrict__ col)
{
    const int e = blockIdx.x * blockDim.x + threadIdx.x;
    if (e < EE) {
        const int p = atomicAdd(&g_cur[row[e]], 1);
        g_ecol[p] = col[e];
    }
}

// ---------------- fused SDDMM + online softmax + SPMM ----------------------
__global__ __launch_bounds__(256)
void attn_kernel(float* __restrict__ out)
{
    const int node = blockIdx.x;
    const int head = threadIdx.x >> 5;
    const int lane = threadIdx.x & 31;
    const int beg = g_off[node];
    const int end = g_off[node + 1];

    const size_t hoff = (size_t)head * DHH + lane * 2;
    const float2 qv = *(const float2*)(g_q + (size_t)node * OUTD + hoff);

    const float NEG = -3.402823466e38f;
    float m1 = NEG, den1 = 0.f;
    float2 acc1 = make_float2(0.f, 0.f);
    float m2 = NEG, den2 = 0.f;
    float2 acc2 = make_float2(0.f, 0.f);

    int j = beg;
    for (; j + 1 < end; j += 2) {
        const int ca = __ldg(g_ecol + j);
        const int cb = __ldg(g_ecol + j + 1);
        const float2 ka = *(const float2*)(g_k + (size_t)ca * OUTD + hoff);
        const float2 kb = *(const float2*)(g_k + (size_t)cb * OUTD + hoff);
        float sa = qv.x * ka.x + qv.y * ka.y;
        float sb = qv.x * kb.x + qv.y * kb.y;
#pragma unroll
        for (int off = 16; off; off >>= 1) {
            sa += __shfl_xor_sync(0xffffffffu, sa, off);
            sb += __shfl_xor_sync(0xffffffffu, sb, off);
        }
        const float2 va = *(const float2*)(g_v + (size_t)ca * OUTD + hoff);
        const float2 vb = *(const float2*)(g_v + (size_t)cb * OUTD + hoff);

        const float mna = fmaxf(m1, sa);
        const float ca1 = __expf(m1 - mna);
        const float pa  = __expf(sa - mna);
        den1   = den1 * ca1 + pa;
        acc1.x = acc1.x * ca1 + pa * va.x;
        acc1.y = acc1.y * ca1 + pa * va.y;
        m1 = mna;

        const float mnb = fmaxf(m2, sb);
        const float cb1 = __expf(m2 - mnb);
        const float pb  = __expf(sb - mnb);
        den2   = den2 * cb1 + pb;
        acc2.x = acc2.x * cb1 + pb * vb.x;
        acc2.y = acc2.y * cb1 + pb * vb.y;
        m2 = mnb;
    }
    if (j < end) {
        const int ca = __ldg(g_ecol + j);
        const float2 ka = *(const float2*)(g_k + (size_t)ca * OUTD + hoff);
        float sa = qv.x * ka.x + qv.y * ka.y;
#pragma unroll
        for (int off = 16; off; off >>= 1)
            sa += __shfl_xor_sync(0xffffffffu, sa, off);
        const float2 va = *(const float2*)(g_v + (size_t)ca * OUTD + hoff);
        const float mna = fmaxf(m1, sa);
        const float ca1 = __expf(m1 - mna);
        const float pa  = __expf(sa - mna);
        den1   = den1 * ca1 + pa;
        acc1.x = acc1.x * ca1 + pa * va.x;
        acc1.y = acc1.y * ca1 + pa * va.y;
        m1 = mna;
    }

    const float mm = fmaxf(m1, m2);
    const float c1 = __expf(m1 - mm);
    const float c2 = __expf(m2 - mm);
    const float den = den1 * c1 + den2 * c2;
    float2 acc;
    acc.x = acc1.x * c1 + acc2.x * c2;
    acc.y = acc1.y * c1 + acc2.y * c2;

    const float inv = (den > 0.f) ? (1.f / den) : 0.f;
    float2 o = make_float2(acc.x * inv, acc.y * inv);
    *(float2*)(out + (size_t)node * OUTD + hoff) = o;
}

// ---------------- launch ----------------------------------------------------
extern "C" void kernel_launch(void* const* d_in, const int* in_sizes, int n_in,
                              void* d_out, int out_size)
{
    const float* h    = (const float*)d_in[0];
    const int*   row  = (const int*)d_in[1];
    const int*   col  = (const int*)d_in[2];
    const float* W_in = (const float*)d_in[3];
    const float* b_in = (const float*)d_in[4];
    const float* W_q  = (const float*)d_in[5];
    const float* b_q  = (const float*)d_in[6];
    const float* W_k  = (const float*)d_in[7];
    const float* b_k  = (const float*)d_in[8];
    const float* W_v  = (const float*)d_in[9];
    const float* b_v  = (const float*)d_in[10];
    float* out = (float*)d_out;

    float *gwr, *gx, *gq, *gk, *gv;
    cudaGetSymbolAddress((void**)&gwr, g_wr);
    cudaGetSymbolAddress((void**)&gx, g_x);
    cudaGetSymbolAddress((void**)&gq, g_q);
    cudaGetSymbolAddress((void**)&gk, g_k);
    cudaGetSymbolAddress((void**)&gv, g_v);

    cudaFuncSetAttribute(gemm_tf32<true>,  cudaFuncAttributeMaxDynamicSharedMemorySize, GSMEM_BYTES);
    cudaFuncSetAttribute(gemm_tf32<false>, cudaFuncAttributeMaxDynamicSharedMemorySize, GSMEM_BYTES);

    // prep: RNA-round the 4 weight matrices (h goes in truncated; x is
    // RNA-rounded at gemm1's epilogue, so GEMMs 2-4 see rounded A and B)
    const int wn4 = OUTD * OUTD / 4;  // 65536
    round_copy4<<<wn4 / 256, 256>>>((const float4*)W_in, (float4*)(gwr + 0 * OUTD * OUTD), wn4);
    round_copy4<<<wn4 / 256, 256>>>((const float4*)W_q,  (float4*)(gwr + 1 * OUTD * OUTD), wn4);
    round_copy4<<<wn4 / 256, 256>>>((const float4*)W_k,  (float4*)(gwr + 2 * OUTD * OUTD), wn4);
    round_copy4<<<wn4 / 256, 256>>>((const float4*)W_v,  (float4*)(gwr + 3 * OUTD * OUTD), wn4);

    const dim3 ggrid(512 / BN, NN / BM);  // (4, 256)
    gemm_tf32<true ><<<ggrid, 128, GSMEM_BYTES>>>(h,  gwr + 0 * OUTD * OUTD, b_in, gx, 1.0f);
    gemm_tf32<false><<<ggrid, 128, GSMEM_BYTES>>>(gx, gwr + 1 * OUTD * OUTD, b_q,  gq, 0.125f);
    gemm_tf32<false><<<ggrid, 128, GSMEM_BYTES>>>(gx, gwr + 2 * OUTD * OUTD, b_k,  gk, 1.0f);
    gemm_tf32<false><<<ggrid, 128, GSMEM_BYTES>>>(gx, gwr + 3 * OUTD * OUTD, b_v,  gv, 1.0f);

    zero_cnt_kernel<<<NN / 256, 256>>>();
    count_kernel<<<EE / 256, 256>>>(row);
    scan_kernel<<<1, 512>>>();
    scatter_kernel<<<EE / 256, 256>>>(row, col);

    attn_kernel<<<NN, 256>>>(out);
}